// round 13
// baseline (speedup 1.0000x reference)
#include <cuda_runtime.h>
#include <math.h>
#include <stdint.h>
#include <stddef.h>

#define NT    768
#define NH    12
#define DIM   384
#define PD    128
#define FEAT  2112
#define NPROJ 1152
#define TI    3
#define NTILE 24
#define SPLITK 6

#define SCALAR_SCALE 0.14433756729740643f
#define POINT_SCALE  0.13608276348795434f
#define PAIR_SCALE   0.57735026918962584f

typedef unsigned long long u64;

__device__ __forceinline__ u64 pk2(float x) {
    u64 r;
    asm("mov.b64 %0, {%1, %1};" : "=l"(r) : "r"(__float_as_uint(x)));
    return r;
}
__device__ __forceinline__ void fma2(u64& a, u64 b, u64 c) {
    asm("fma.rn.f32x2 %0, %1, %2, %0;" : "+l"(a) : "l"(b), "l"(c));
}
__device__ __forceinline__ void mul2(u64& a, u64 b) {
    asm("mul.rn.f32x2 %0, %0, %1;" : "+l"(a) : "l"(b));
}
__device__ __forceinline__ float2 unpk(u64 a) {
    float2 r;
    asm("mov.b64 {%0, %1}, %2;" : "=f"(r.x), "=f"(r.y) : "l"(a));
    return r;
}

// ------------- device scratch -------------
__device__ __align__(16) float g_wall [DIM * NPROJ];
__device__ __align__(16) float g_proj [NT * NPROJ];
__device__ __align__(16) float g_qs   [NH * NT * 16];
__device__ __align__(16) float g_ks   [NH * NT * 16];
__device__ __align__(16) float g_vs   [NH * NT * 16];
__device__ __align__(16) float g_qpg  [NH * NT * 12];
__device__ __align__(16) float g_kpg  [NH * NT * 12];
__device__ __align__(16) float g_vpg  [NH * NT * 24];
__device__ __align__(16) float g_feats[(size_t)NT * FEAT];
__device__ __align__(16) float g_part [SPLITK * NT * DIM];

// ------------- pack weights -------------
__global__ __launch_bounds__(256) void pack_w(
    const float* __restrict__ Wq,  const float* __restrict__ Wk,
    const float* __restrict__ Wv,  const float* __restrict__ Wpq,
    const float* __restrict__ Wpk, const float* __restrict__ Wpv)
{
    int e = blockIdx.x * 256 + threadIdx.x;
    if (e >= DIM * NPROJ) return;
    int r = e / NPROJ, c = e % NPROJ;
    float v;
    if      (c < 192) v = Wq [r*192 + c];
    else if (c < 384) v = Wk [r*192 + (c-192)];
    else if (c < 576) v = Wv [r*192 + (c-384)];
    else if (c < 720) v = Wpq[r*144 + (c-576)];
    else if (c < 864) v = Wpk[r*144 + (c-720)];
    else              v = Wpv[r*288 + (c-864)];
    g_wall[e] = v;
}

// ------------- split-K SGEMM -------------
__global__ __launch_bounds__(128) void sgemm_sk(
    const float* __restrict__ A, const float* __restrict__ B,
    float* __restrict__ C, int M, int N, int K)
{
    __shared__ float As[16][64];
    __shared__ float Bs[16][68];
    const int tid = threadIdx.x;
    const int tx = tid & 15, ty = tid >> 4;
    const int row0 = blockIdx.y * 64, col0 = blockIdx.x * 64;
    const int kchunk = K / gridDim.z;
    const int kbeg = blockIdx.z * kchunk;

    float acc[8][4];
#pragma unroll
    for (int m = 0; m < 8; m++)
#pragma unroll
        for (int n = 0; n < 4; n++) acc[m][n] = 0.f;

    for (int k0 = kbeg; k0 < kbeg + kchunk; k0 += 16) {
        for (int e = tid; e < 256; e += 128) {
            int r = e >> 2, c4 = e & 3;
            float4 v = *reinterpret_cast<const float4*>(
                &A[(size_t)(row0+r)*K + k0 + c4*4]);
            As[c4*4+0][r] = v.x; As[c4*4+1][r] = v.y;
            As[c4*4+2][r] = v.z; As[c4*4+3][r] = v.w;
        }
        for (int e = tid; e < 256; e += 128) {
            int r = e >> 4, c4 = e & 15;
            *reinterpret_cast<float4*>(&Bs[r][c4*4]) =
                *reinterpret_cast<const float4*>(
                    &B[(size_t)(k0+r)*N + col0 + c4*4]);
        }
        __syncthreads();
#pragma unroll
        for (int kk = 0; kk < 16; kk++) {
            float a[8];
#pragma unroll
            for (int m = 0; m < 8; m++) a[m] = As[kk][ty*8 + m];
            float4 b = *reinterpret_cast<const float4*>(&Bs[kk][tx*4]);
#pragma unroll
            for (int m = 0; m < 8; m++) {
                acc[m][0] += a[m]*b.x; acc[m][1] += a[m]*b.y;
                acc[m][2] += a[m]*b.z; acc[m][3] += a[m]*b.w;
            }
        }
        __syncthreads();
    }
    float* Cz = C + (size_t)blockIdx.z * M * N;
#pragma unroll
    for (int m = 0; m < 8; m++) {
        int r = row0 + ty*8 + m;
        float4 v = make_float4(acc[m][0], acc[m][1], acc[m][2], acc[m][3]);
        *reinterpret_cast<float4*>(&Cz[(size_t)r*N + col0 + tx*4]) = v;
    }
}

// ------------- split-K reduce (+ output bias) -------------
__global__ __launch_bounds__(256) void reduce_k(
    float* __restrict__ out, const float* __restrict__ bout)
{
    int e = blockIdx.x * 256 + threadIdx.x;
    if (e >= NT * DIM) return;
    float s = 0.f;
#pragma unroll
    for (int z = 0; z < SPLITK; z++) s += g_part[(size_t)z*NT*DIM + e];
    out[e] = s + bout[e % DIM];
}

// ------------- relayout + rotate points to global frame -------------
__global__ __launch_bounds__(128) void relayout(
    const float* __restrict__ rot, const float* __restrict__ trans)
{
    const int i = blockIdx.x, t = threadIdx.x;
    __shared__ float R[9], tv[3];
    if (t < 9) R[t]  = rot[i*9 + t];
    if (t < 3) tv[t] = trans[i*3 + t];
    __syncthreads();
    const float* pr = g_proj + (size_t)i * NPROJ;
    for (int e = t; e < NH*16; e += 128) {
        int h = e/16, d = e%16;
        g_qs[((size_t)h*NT+i)*16+d] = pr[      h*16+d];
        g_ks[((size_t)h*NT+i)*16+d] = pr[192 + h*16+d];
        g_vs[((size_t)h*NT+i)*16+d] = pr[384 + h*16+d];
    }
    for (int e = t; e < NH*4; e += 128) {
        int h = e/4, p = e%4;
        const float* s = pr + 576 + h*12 + p*3;
        float x=s[0], y=s[1], z=s[2];
        float* o = g_qpg + ((size_t)h*NT+i)*12 + p*3;
        o[0]=R[0]*x+R[1]*y+R[2]*z+tv[0];
        o[1]=R[3]*x+R[4]*y+R[5]*z+tv[1];
        o[2]=R[6]*x+R[7]*y+R[8]*z+tv[2];
        s = pr + 720 + h*12 + p*3; x=s[0]; y=s[1]; z=s[2];
        o = g_kpg + ((size_t)h*NT+i)*12 + p*3;
        o[0]=R[0]*x+R[1]*y+R[2]*z+tv[0];
        o[1]=R[3]*x+R[4]*y+R[5]*z+tv[1];
        o[2]=R[6]*x+R[7]*y+R[8]*z+tv[2];
    }
    for (int e = t; e < NH*8; e += 128) {
        int h = e/8, p = e%8;
        const float* s = pr + 864 + h*24 + p*3;
        float x=s[0], y=s[1], z=s[2];
        float* o = g_vpg + ((size_t)h*NT+i)*24 + p*3;
        o[0]=R[0]*x+R[1]*y+R[2]*z+tv[0];
        o[1]=R[3]*x+R[4]*y+R[5]*z+tv[1];
        o[2]=R[6]*x+R[7]*y+R[8]*z+tv[2];
    }
}

// ------------- fused attention + pair-bias (permuted tile + f32x2) --------
// prs column permutation: logical float4 c4 stored at cell (c4>>1)+(c4&1)*16.
// Dot products (bias) are permutation-invariant when wTs uses the same perm.
#define PRS_OFF 0                    // [3][32][132]
#define ACC_OFF 12672                // [3][12][168]
#define PPS_OFF 18720                // [3][12] rows, stride 33
#define QSS_OFF 19908
#define QPS_OFF 20484
#define MST_OFF 20916
#define LST_OFF 20952
#define FAC_OFF 20988
#define RS_OFF  21024
#define TV_OFF  21051
#define WT_OFF  21060                // [12][132] permuted transposed Wpb
#define BB_OFF  22644
#define BT_OFF  22656                // [3][12] rows, stride 33
#define SMEM_FLOATS 23844

__global__ __launch_bounds__(384, 2) void attn_k(
    const float* __restrict__ pair, const float* __restrict__ rot,
    const float* __restrict__ trans, const float* __restrict__ pwts,
    const float* __restrict__ Wpb, const float* __restrict__ bpb)
{
    extern __shared__ float sm[];
    float* prs  = sm + PRS_OFF;
    float* accs = sm + ACC_OFF;
    float* pps  = sm + PPS_OFF;
    float* qss  = sm + QSS_OFF;
    float* qps  = sm + QPS_OFF;
    float* mst  = sm + MST_OFF;
    float* lst  = sm + LST_OFF;
    float* facs = sm + FAC_OFF;
    float* Rs   = sm + RS_OFF;
    float* tvs  = sm + TV_OFF;
    float* wTs  = sm + WT_OFF;
    float* bbs  = sm + BB_OFF;
    float* bts  = sm + BT_OFF;

    const int i0 = blockIdx.x * TI;
    const int t  = threadIdx.x;
    const int h  = t >> 5, lane = t & 31;

    // pair-accumulate roles: (3 heads x 2 cells)/thread
    const int cp   = t & 15;          // cell pair: cells cp and cp+16
    const int hgrp = (t >> 4) & 3;    // heads 3*hgrp .. 3*hgrp+2
    const int jq   = (t >> 6) & 1;    // j half
    const int qq   = t >> 7;          // query 0..2
    // scalar/point roles
    const bool has_sp = (t < 360);
    const int q2  = t % 3;
    const int u3  = t / 3;
    const int hh2 = u3 / 10;
    const int c2  = u3 % 10;
    const float* vbase;
    int vstride;
    if (c2 < 4) { vbase = g_vs  + (size_t)hh2*NT*16 + c2*4;     vstride = 16; }
    else        { vbase = g_vpg + (size_t)hh2*NT*24 + (c2-4)*4; vstride = 24; }
    // bias roles (full width): row = t>>2, head-triple = t&3
    const int brow = t >> 2;
    const int bg   = t & 3;
    const int bq_  = brow >> 5, br_ = brow & 31;

    u64 pacc[3][4];                   // [head][va.x va.y vb.x vb.y]
#pragma unroll
    for (int m = 0; m < 3; m++)
#pragma unroll
        for (int k = 0; k < 4; k++) pacc[m][k] = 0ull;
    u64 spx = 0ull, spy = 0ull;

    for (int e = t; e < TI*NH*16;  e += 384) {
        int q = e / (NH*16), rem = e % (NH*16);
        qss[e] = g_qs[((size_t)(rem/16)*NT + i0 + q)*16 + rem%16];
    }
    for (int e = t; e < TI*NH*12;  e += 384) {
        int q = e / (NH*12), rem = e % (NH*12);
        qps[e] = g_qpg[((size_t)(rem/12)*NT + i0 + q)*12 + rem%12];
    }
    for (int e = t; e < NH*PD; e += 384) {   // permuted wT fill
        int hh = e >> 7, d = e & 127;
        int c4 = d >> 2, pc = (c4 >> 1) + (c4 & 1)*16;
        wTs[hh*132 + pc*4 + (d & 3)] = Wpb[d*12 + hh];
    }
    if (t < NH) bbs[t] = bpb[t];
    if (t < TI*NH) { mst[t] = -1e30f; lst[t] = 0.f; }
    if (t < TI*9)  Rs[t]  = rot[(i0 + t/9)*9 + t%9];
    if (t < TI*3)  tvs[t] = trans[(i0 + t/3)*3 + t%3];
    __syncthreads();

    float wv = pwts[h];
    float pwh = (wv > 20.f) ? wv : log1pf(expf(wv));
    const float pscale = -0.5f * POINT_SCALE * pwh;

    for (int jt = 0; jt < NTILE; jt++) {
        const int j0 = jt * 32;
        // ---- stage pair tiles with column permutation ----
#pragma unroll
        for (int u = 0; u < 8; u++) {
            int e = t + u*384;
            int q = e >> 10, rem = e & 1023;
            int r = rem >> 5, c = rem & 31;
            int pc = (c >> 1) + (c & 1)*16;
            float4 v = *reinterpret_cast<const float4*>(
                pair + ((size_t)(i0+q)*NT + j0 + r)*PD + c*4);
            *reinterpret_cast<float4*>(&prs[(q*32 + r)*132 + pc*4]) = v;
        }
        __syncthreads();
        // ---- K loads issued early ----
        const int j = j0 + lane;
        const float4* krp = reinterpret_cast<const float4*>(g_ks  + ((size_t)h*NT + j)*16);
        const float4* kpp = reinterpret_cast<const float4*>(g_kpg + ((size_t)h*NT + j)*12);
        float4 k0 = krp[0], k1 = krp[1], k2 = krp[2], k3 = krp[3];
        float4 p0 = kpp[0], p1 = kpp[1], p2 = kpp[2];
        // ---- fused pair-bias (dot is perm-invariant) ----
        {
            const float* w0 = wTs + (3*bg+0)*132;
            const float* w1 = wTs + (3*bg+1)*132;
            const float* w2 = wTs + (3*bg+2)*132;
            const float* prow = prs + brow*132;
            float b0 = 0.f, b1 = 0.f, b2 = 0.f;
#pragma unroll 8
            for (int k4 = 0; k4 < 32; k4++) {
                float4 v  = *reinterpret_cast<const float4*>(prow + k4*4);
                float4 wa = *reinterpret_cast<const float4*>(w0 + k4*4);
                float4 wb = *reinterpret_cast<const float4*>(w1 + k4*4);
                float4 wc = *reinterpret_cast<const float4*>(w2 + k4*4);
                b0 += v.x*wa.x + v.y*wa.y + v.z*wa.z + v.w*wa.w;
                b1 += v.x*wb.x + v.y*wb.y + v.z*wb.z + v.w*wb.w;
                b2 += v.x*wc.x + v.y*wc.y + v.z*wc.z + v.w*wc.w;
            }
            bts[(bq_*NH + 3*bg+0)*33 + br_] = (b0 + bbs[3*bg+0]) * PAIR_SCALE;
            bts[(bq_*NH + 3*bg+1)*33 + br_] = (b1 + bbs[3*bg+1]) * PAIR_SCALE;
            bts[(bq_*NH + 3*bg+2)*33 + br_] = (b2 + bbs[3*bg+2]) * PAIR_SCALE;
        }
        __syncthreads();
        // ---- logits + interleaved 3-q online softmax ----
        {
            float s[TI];
#pragma unroll
            for (int q = 0; q < TI; q++) {
                const float4* qsv = reinterpret_cast<const float4*>(qss + (q*NH + h)*16);
                const float4* qpv = reinterpret_cast<const float4*>(qps + (q*NH + h)*12);
                float4 a0 = qsv[0], a1 = qsv[1], a2 = qsv[2], a3 = qsv[3];
                float sv = a0.x*k0.x + a0.y*k0.y + a0.z*k0.z + a0.w*k0.w
                         + a1.x*k1.x + a1.y*k1.y + a1.z*k1.z + a1.w*k1.w
                         + a2.x*k2.x + a2.y*k2.y + a2.z*k2.z + a2.w*k2.w
                         + a3.x*k3.x + a3.y*k3.y + a3.z*k3.z + a3.w*k3.w;
                sv *= SCALAR_SCALE;
                float4 b0 = qpv[0], b1 = qpv[1], b2 = qpv[2];
                float dx, dist = 0.f;
                dx = b0.x-p0.x; dist += dx*dx; dx = b0.y-p0.y; dist += dx*dx;
                dx = b0.z-p0.z; dist += dx*dx; dx = b0.w-p0.w; dist += dx*dx;
                dx = b1.x-p1.x; dist += dx*dx; dx = b1.y-p1.y; dist += dx*dx;
                dx = b1.z-p1.z; dist += dx*dx; dx = b1.w-p1.w; dist += dx*dx;
                dx = b2.x-p2.x; dist += dx*dx; dx = b2.y-p2.y; dist += dx*dx;
                dx = b2.z-p2.z; dist += dx*dx; dx = b2.w-p2.w; dist += dx*dx;
                sv += pscale * dist;
                sv += bts[(q*NH + h)*33 + lane];
                s[q] = sv;
            }
            float mx[TI];
#pragma unroll
            for (int q = 0; q < TI; q++) mx[q] = s[q];
#pragma unroll
            for (int o = 16; o; o >>= 1) {
#pragma unroll
                for (int q = 0; q < TI; q++)
                    mx[q] = fmaxf(mx[q], __shfl_xor_sync(~0u, mx[q], o));
            }
            float mold[TI], mnew[TI], ps[TI];
#pragma unroll
            for (int q = 0; q < TI; q++) {
                mold[q] = mst[q*NH + h];
                mnew[q] = fmaxf(mold[q], mx[q]);
                float p = __expf(s[q] - mnew[q]);
                pps[(q*NH + h)*33 + lane] = p;
                ps[q] = p;
            }
#pragma unroll
            for (int o = 16; o; o >>= 1) {
#pragma unroll
                for (int q = 0; q < TI; q++)
                    ps[q] += __shfl_xor_sync(~0u, ps[q], o);
            }
            if (lane == 0) {
#pragma unroll
                for (int q = 0; q < TI; q++) {
                    float f = __expf(mold[q] - mnew[q]);
                    facs[q*NH + h] = f;
                    lst[q*NH + h] = lst[q*NH + h]*f + ps[q];
                    mst[q*NH + h] = mnew[q];
                }
            }
        }
        __syncthreads();
        // ---- pair accumulate: 3 heads x 2 cells, f32x2 FMAs ----
        {
            const float* fq = facs + qq*NH + 3*hgrp;
#pragma unroll
            for (int m = 0; m < 3; m++) {
                u64 fp = pk2(fq[m]);
                mul2(pacc[m][0], fp); mul2(pacc[m][1], fp);
                mul2(pacc[m][2], fp); mul2(pacc[m][3], fp);
            }
            const float* pbase = pps + (qq*NH + 3*hgrp)*33 + jq*16;
            const float* prow  = prs + (qq*32 + jq*16)*132 + cp*4;
#pragma unroll
            for (int jj = 0; jj < 16; jj++) {
                ulonglong2 va = *reinterpret_cast<const ulonglong2*>(prow + jj*132);
                ulonglong2 vb = *reinterpret_cast<const ulonglong2*>(prow + jj*132 + 64);
                u64 pa = pk2(pbase[jj]);
                u64 pb = pk2(pbase[33 + jj]);
                u64 pc = pk2(pbase[66 + jj]);
                fma2(pacc[0][0], pa, va.x); fma2(pacc[0][1], pa, va.y);
                fma2(pacc[0][2], pa, vb.x); fma2(pacc[0][3], pa, vb.y);
                fma2(pacc[1][0], pb, va.x); fma2(pacc[1][1], pb, va.y);
                fma2(pacc[1][2], pb, vb.x); fma2(pacc[1][3], pb, vb.y);
                fma2(pacc[2][0], pc, va.x); fma2(pacc[2][1], pc, va.y);
                fma2(pacc[2][2], pc, vb.x); fma2(pacc[2][3], pc, vb.y);
            }
        }
        // ---- scalar/point accumulate (f32x2) ----
        if (has_sp) {
            u64 fp = pk2(facs[q2*NH + hh2]);
            mul2(spx, fp); mul2(spy, fp);
            const float* pph = pps + (q2*NH + hh2)*33;
            const float* src = vbase + (size_t)j0*vstride;
#pragma unroll 8
            for (int jv = 0; jv < 32; jv++) {
                ulonglong2 v = *reinterpret_cast<const ulonglong2*>(src + (size_t)jv*vstride);
                u64 pp = pk2(pph[jv]);
                fma2(spx, pp, v.x);
                fma2(spy, pp, v.y);
            }
        }
        __syncthreads();
    }

    // ---- merge register accumulators ----
    {
        // thread's cells cp, cp+16 = logical float4 cols 2cp, 2cp+1 = floats cp*8..+7
        if (jq == 0) {
#pragma unroll
            for (int m = 0; m < 3; m++) {
                float* dst = accs + (qq*NH + 3*hgrp + m)*168 + 40 + cp*8;
                ulonglong2 w0; w0.x = pacc[m][0]; w0.y = pacc[m][1];
                ulonglong2 w1; w1.x = pacc[m][2]; w1.y = pacc[m][3];
                *reinterpret_cast<ulonglong2*>(dst)     = w0;
                *reinterpret_cast<ulonglong2*>(dst + 4) = w1;
            }
        }
        if (has_sp) {
            int off = (c2 < 4) ? c2*4 : 16 + (c2-4)*4;
            ulonglong2 w; w.x = spx; w.y = spy;
            *reinterpret_cast<ulonglong2*>(accs + (q2*NH + hh2)*168 + off) = w;
        }
        __syncthreads();
        if (jq == 1) {
#pragma unroll
            for (int m = 0; m < 3; m++) {
                float* dst = accs + (qq*NH + 3*hgrp + m)*168 + 40 + cp*8;
#pragma unroll
                for (int k = 0; k < 4; k++) {
                    float2 a = unpk(pacc[m][k]);
                    dst[k*2 + 0] += a.x;
                    dst[k*2 + 1] += a.y;
                }
            }
        }
        __syncthreads();
    }

    // ---- finalize ----
    for (int e = t; e < TI*NH*16; e += 384) {
        int q = e / (NH*16), rem = e % (NH*16);
        int hh = rem/16, d = rem%16;
        g_feats[(size_t)(i0+q)*FEAT + hh*16 + d] =
            accs[(q*NH+hh)*168 + d] / lst[q*NH+hh];
    }
    for (int e = t; e < TI*NH*8; e += 384) {
        int q = e / (NH*8), rem = e % (NH*8);
        int hh = rem/8, p = rem%8;
        float inv = 1.f / lst[q*NH+hh];
        const float* R = Rs + q*9;
        const float* tv = tvs + q*3;
        const float* ac = accs + (q*NH+hh)*168 + 16 + p*3;
        float gx = ac[0]*inv - tv[0];
        float gy = ac[1]*inv - tv[1];
        float gz = ac[2]*inv - tv[2];
        float lx = R[0]*gx + R[3]*gy + R[6]*gz;
        float ly = R[1]*gx + R[4]*gy + R[7]*gz;
        float lz = R[2]*gx + R[5]*gy + R[8]*gz;
        float* fo = g_feats + (size_t)(i0+q)*FEAT;
        fo[192 + hh*24 + p*3 + 0] = lx;
        fo[192 + hh*24 + p*3 + 1] = ly;
        fo[192 + hh*24 + p*3 + 2] = lz;
        fo[480 + hh*8 + p] = sqrtf(lx*lx + ly*ly + lz*lz + 1e-8f);
    }
    for (int e = t; e < TI*NH*PD; e += 384) {
        int q = e / (NH*PD), rem = e % (NH*PD);
        int hh = rem/PD, d = rem%PD;
        g_feats[(size_t)(i0+q)*FEAT + 576 + hh*PD + d] =
            accs[(q*NH+hh)*168 + 40 + d] / lst[q*NH+hh];
    }
}

// ------------- launch -------------
extern "C" void kernel_launch(void* const* d_in, const int* in_sizes, int n_in,
                              void* d_out, int out_size)
{
    (void)in_sizes; (void)n_in; (void)out_size;
    const float* x     = (const float*)d_in[0];
    const float* pair  = (const float*)d_in[1];
    const float* rot   = (const float*)d_in[2];
    const float* trans = (const float*)d_in[3];
    const float* Wq    = (const float*)d_in[4];
    const float* Wk    = (const float*)d_in[5];
    const float* Wv    = (const float*)d_in[6];
    const float* Wpq   = (const float*)d_in[7];
    const float* Wpk   = (const float*)d_in[8];
    const float* Wpv   = (const float*)d_in[9];
    const float* Wpb   = (const float*)d_in[10];
    const float* bpb   = (const float*)d_in[11];
    const float* pwts  = (const float*)d_in[12];
    const float* Wout  = (const float*)d_in[13];
    const float* bout  = (const float*)d_in[14];
    float* out = (float*)d_out;

    cudaFuncSetAttribute(attn_k, cudaFuncAttributeMaxDynamicSharedMemorySize,
                         SMEM_FLOATS * 4);

    void *p_wall, *p_proj, *p_feats, *p_part;
    cudaGetSymbolAddress(&p_wall,  g_wall);
    cudaGetSymbolAddress(&p_proj,  g_proj);
    cudaGetSymbolAddress(&p_feats, g_feats);
    cudaGetSymbolAddress(&p_part,  g_part);

    pack_w<<<(DIM*NPROJ + 255)/256, 256>>>(Wq, Wk, Wv, Wpq, Wpk, Wpv);
    {
        dim3 g(NPROJ/64, NT/64, 1);
        sgemm_sk<<<g, 128>>>(x, (const float*)p_wall, (float*)p_proj,
                             NT, NPROJ, DIM);
    }
    relayout<<<NT, 128>>>(rot, trans);
    attn_k<<<NT/TI, 384, SMEM_FLOATS*4>>>(pair, rot, trans, pwts, Wpb, bpb);
    {
        dim3 g(DIM/64, NT/64, SPLITK);
        sgemm_sk<<<g, 128>>>((const float*)p_feats, Wout, (float*)p_part,
                             NT, DIM, FEAT);
    }
    reduce_k<<<(NT*DIM + 255)/256, 256>>>(out, bout);
}

// round 15
// speedup vs baseline: 1.0238x; 1.0238x over previous
#include <cuda_runtime.h>
#include <math.h>
#include <stdint.h>
#include <stddef.h>

#define NT    768
#define NH    12
#define DIM   384
#define PD    128
#define FEAT  2112
#define NPROJ 1152
#define TI    3
#define NTILE 24
#define SPLITK 6

#define SCALAR_SCALE 0.14433756729740643f
#define POINT_SCALE  0.13608276348795434f
#define PAIR_SCALE   0.57735026918962584f

__device__ __forceinline__ uint32_t cvt_tf32(float x) {
    uint32_t r;
    asm("cvt.rna.tf32.f32 %0, %1;" : "=r"(r) : "f"(x));
    return r;
}
__device__ __forceinline__ void mma_tf32(
    float& c0, float& c1, float& c2, float& c3,
    uint32_t a0, uint32_t a1, uint32_t a2, uint32_t a3,
    uint32_t b0, uint32_t b1)
{
    asm volatile(
        "mma.sync.aligned.m16n8k8.row.col.f32.tf32.tf32.f32 "
        "{%0,%1,%2,%3}, {%4,%5,%6,%7}, {%8,%9}, {%0,%1,%2,%3};"
        : "+f"(c0), "+f"(c1), "+f"(c2), "+f"(c3)
        : "r"(a0), "r"(a1), "r"(a2), "r"(a3), "r"(b0), "r"(b1));
}

// ------------- device scratch -------------
__device__ __align__(16) float g_wall [DIM * NPROJ];
__device__ __align__(16) float g_proj [NT * NPROJ];
__device__ __align__(16) float g_qs   [NH * NT * 16];
__device__ __align__(16) float g_ks   [NH * NT * 16];
__device__ __align__(16) float g_vs   [NH * NT * 16];
__device__ __align__(16) float g_qpg  [NH * NT * 12];
__device__ __align__(16) float g_kpg  [NH * NT * 12];
__device__ __align__(16) float g_vpg  [NH * NT * 24];
__device__ __align__(16) float g_feats[(size_t)NT * FEAT];
__device__ __align__(16) float g_part [SPLITK * NT * DIM];

// ------------- pack weights -------------
__global__ __launch_bounds__(256) void pack_w(
    const float* __restrict__ Wq,  const float* __restrict__ Wk,
    const float* __restrict__ Wv,  const float* __restrict__ Wpq,
    const float* __restrict__ Wpk, const float* __restrict__ Wpv)
{
    int e = blockIdx.x * 256 + threadIdx.x;
    if (e >= DIM * NPROJ) return;
    int r = e / NPROJ, c = e % NPROJ;
    float v;
    if      (c < 192) v = Wq [r*192 + c];
    else if (c < 384) v = Wk [r*192 + (c-192)];
    else if (c < 576) v = Wv [r*192 + (c-384)];
    else if (c < 720) v = Wpq[r*144 + (c-576)];
    else if (c < 864) v = Wpk[r*144 + (c-720)];
    else              v = Wpv[r*288 + (c-864)];
    g_wall[e] = v;
}

// ------------- split-K SGEMM -------------
__global__ __launch_bounds__(128) void sgemm_sk(
    const float* __restrict__ A, const float* __restrict__ B,
    float* __restrict__ C, int M, int N, int K)
{
    __shared__ float As[16][64];
    __shared__ float Bs[16][68];
    const int tid = threadIdx.x;
    const int tx = tid & 15, ty = tid >> 4;
    const int row0 = blockIdx.y * 64, col0 = blockIdx.x * 64;
    const int kchunk = K / gridDim.z;
    const int kbeg = blockIdx.z * kchunk;

    float acc[8][4];
#pragma unroll
    for (int m = 0; m < 8; m++)
#pragma unroll
        for (int n = 0; n < 4; n++) acc[m][n] = 0.f;

    for (int k0 = kbeg; k0 < kbeg + kchunk; k0 += 16) {
        for (int e = tid; e < 256; e += 128) {
            int r = e >> 2, c4 = e & 3;
            float4 v = *reinterpret_cast<const float4*>(
                &A[(size_t)(row0+r)*K + k0 + c4*4]);
            As[c4*4+0][r] = v.x; As[c4*4+1][r] = v.y;
            As[c4*4+2][r] = v.z; As[c4*4+3][r] = v.w;
        }
        for (int e = tid; e < 256; e += 128) {
            int r = e >> 4, c4 = e & 15;
            *reinterpret_cast<float4*>(&Bs[r][c4*4]) =
                *reinterpret_cast<const float4*>(
                    &B[(size_t)(k0+r)*N + col0 + c4*4]);
        }
        __syncthreads();
#pragma unroll
        for (int kk = 0; kk < 16; kk++) {
            float a[8];
#pragma unroll
            for (int m = 0; m < 8; m++) a[m] = As[kk][ty*8 + m];
            float4 b = *reinterpret_cast<const float4*>(&Bs[kk][tx*4]);
#pragma unroll
            for (int m = 0; m < 8; m++) {
                acc[m][0] += a[m]*b.x; acc[m][1] += a[m]*b.y;
                acc[m][2] += a[m]*b.z; acc[m][3] += a[m]*b.w;
            }
        }
        __syncthreads();
    }
    float* Cz = C + (size_t)blockIdx.z * M * N;
#pragma unroll
    for (int m = 0; m < 8; m++) {
        int r = row0 + ty*8 + m;
        float4 v = make_float4(acc[m][0], acc[m][1], acc[m][2], acc[m][3]);
        *reinterpret_cast<float4*>(&Cz[(size_t)r*N + col0 + tx*4]) = v;
    }
}

// ------------- split-K reduce (+ output bias) -------------
__global__ __launch_bounds__(256) void reduce_k(
    float* __restrict__ out, const float* __restrict__ bout)
{
    int e = blockIdx.x * 256 + threadIdx.x;
    if (e >= NT * DIM) return;
    float s = 0.f;
#pragma unroll
    for (int z = 0; z < SPLITK; z++) s += g_part[(size_t)z*NT*DIM + e];
    out[e] = s + bout[e % DIM];
}

// ------------- relayout + rotate points to global frame -------------
__global__ __launch_bounds__(128) void relayout(
    const float* __restrict__ rot, const float* __restrict__ trans)
{
    const int i = blockIdx.x, t = threadIdx.x;
    __shared__ float R[9], tv[3];
    if (t < 9) R[t]  = rot[i*9 + t];
    if (t < 3) tv[t] = trans[i*3 + t];
    __syncthreads();
    const float* pr = g_proj + (size_t)i * NPROJ;
    for (int e = t; e < NH*16; e += 128) {
        int h = e/16, d = e%16;
        g_qs[((size_t)h*NT+i)*16+d] = pr[      h*16+d];
        g_ks[((size_t)h*NT+i)*16+d] = pr[192 + h*16+d];
        g_vs[((size_t)h*NT+i)*16+d] = pr[384 + h*16+d];
    }
    for (int e = t; e < NH*4; e += 128) {
        int h = e/4, p = e%4;
        const float* s = pr + 576 + h*12 + p*3;
        float x=s[0], y=s[1], z=s[2];
        float* o = g_qpg + ((size_t)h*NT+i)*12 + p*3;
        o[0]=R[0]*x+R[1]*y+R[2]*z+tv[0];
        o[1]=R[3]*x+R[4]*y+R[5]*z+tv[1];
        o[2]=R[6]*x+R[7]*y+R[8]*z+tv[2];
        s = pr + 720 + h*12 + p*3; x=s[0]; y=s[1]; z=s[2];
        o = g_kpg + ((size_t)h*NT+i)*12 + p*3;
        o[0]=R[0]*x+R[1]*y+R[2]*z+tv[0];
        o[1]=R[3]*x+R[4]*y+R[5]*z+tv[1];
        o[2]=R[6]*x+R[7]*y+R[8]*z+tv[2];
    }
    for (int e = t; e < NH*8; e += 128) {
        int h = e/8, p = e%8;
        const float* s = pr + 864 + h*24 + p*3;
        float x=s[0], y=s[1], z=s[2];
        float* o = g_vpg + ((size_t)h*NT+i)*24 + p*3;
        o[0]=R[0]*x+R[1]*y+R[2]*z+tv[0];
        o[1]=R[3]*x+R[4]*y+R[5]*z+tv[1];
        o[2]=R[6]*x+R[7]*y+R[8]*z+tv[2];
    }
}

// ------------- fused attention: tf32 tensor-core pair-accumulate ----------
#define PRS_OFF 0                    // [3][32][132]
#define ACC_OFF 12672                // [3][12][168]
#define PPS_OFF 18720                // [3][16] rows (pad 12..15 zero), stride 33
#define QSS_OFF 20304
#define QPS_OFF 20880
#define MST_OFF 21312                // [3][12]
#define LST_OFF 21348
#define FAC_OFF 21384                // [3][16], pads = 1.0
#define RS_OFF  21432
#define TV_OFF  21459
#define WT_OFF  21468                // [12][132]
#define BB_OFF  23052
#define BT_OFF  23064                // [3][12] rows, stride 33
#define SMEM_FLOATS 24252

__global__ __launch_bounds__(384, 2) void attn_k(
    const float* __restrict__ pair, const float* __restrict__ rot,
    const float* __restrict__ trans, const float* __restrict__ pwts,
    const float* __restrict__ Wpb, const float* __restrict__ bpb)
{
    extern __shared__ float sm[];
    float* prs  = sm + PRS_OFF;
    float* accs = sm + ACC_OFF;
    float* pps  = sm + PPS_OFF;
    float* qss  = sm + QSS_OFF;
    float* qps  = sm + QPS_OFF;
    float* mst  = sm + MST_OFF;
    float* lst  = sm + LST_OFF;
    float* facs = sm + FAC_OFF;
    float* Rs   = sm + RS_OFF;
    float* tvs  = sm + TV_OFF;
    float* wTs  = sm + WT_OFF;
    float* bbs  = sm + BB_OFF;
    float* bts  = sm + BT_OFF;

    const int i0 = blockIdx.x * TI;
    const int t  = threadIdx.x;
    const int h  = t >> 5, lane = t & 31;

    // mma roles: warp = (q=warp/4, n-quadrant=warp%4); 4 n-tiles of 8 cols
    const int qm = h >> 2;
    const int wn = h & 3;
    const int mr = lane >> 2;         // fragment row group 0..7
    const int mc = lane & 3;          // fragment col group 0..3
    // scalar/point roles: q-triples adjacent for V-load broadcast
    const bool has_sp = (t < 360);
    const int q2  = t % 3;
    const int u3  = t / 3;
    const int hh2 = u3 / 10;
    const int c2  = u3 % 10;
    const float* vbase;
    int vstride;
    if (c2 < 4) { vbase = g_vs  + (size_t)hh2*NT*16 + c2*4;     vstride = 16; }
    else        { vbase = g_vpg + (size_t)hh2*NT*24 + (c2-4)*4; vstride = 24; }

    float cfr[4][4];                  // [n-tile][c0..c3] fp32 accum fragments
#pragma unroll
    for (int nt = 0; nt < 4; nt++)
#pragma unroll
        for (int k = 0; k < 4; k++) cfr[nt][k] = 0.f;
    float4 spacc = make_float4(0.f,0.f,0.f,0.f);

    for (int e = t; e < TI*NH*16;  e += 384) {
        int q = e / (NH*16), rem = e % (NH*16);
        qss[e] = g_qs[((size_t)(rem/16)*NT + i0 + q)*16 + rem%16];
    }
    for (int e = t; e < TI*NH*12;  e += 384) {
        int q = e / (NH*12), rem = e % (NH*12);
        qps[e] = g_qpg[((size_t)(rem/12)*NT + i0 + q)*12 + rem%12];
    }
    for (int e = t; e < NH*PD; e += 384)
        wTs[(e >> 7)*132 + (e & 127)] = Wpb[(e & 127)*12 + (e >> 7)];
    for (int e = t; e < TI*16*33; e += 384) pps[e] = 0.f;   // incl pad rows
    if (t < NH) bbs[t] = bpb[t];
    if (t < TI*NH) { mst[t] = -1e30f; lst[t] = 0.f; }
    if (t < TI*16) facs[t] = 1.f;
    if (t < TI*9)  Rs[t]  = rot[(i0 + t/9)*9 + t%9];
    if (t < TI*3)  tvs[t] = trans[(i0 + t/3)*3 + t%3];
    __syncthreads();

    float wv = pwts[h];
    float pwh = (wv > 20.f) ? wv : log1pf(expf(wv));
    const float pscale = -0.5f * POINT_SCALE * pwh;

    for (int jt = 0; jt < NTILE; jt++) {
        const int j0 = jt * 32;
        // ---- stage pair tiles (8 LDGs in flight) ----
#pragma unroll
        for (int u = 0; u < 8; u++) {
            int e = t + u*384;
            int q = e >> 10, rem = e & 1023;
            int r = rem >> 5, c = rem & 31;
            float4 v = *reinterpret_cast<const float4*>(
                pair + ((size_t)(i0+q)*NT + j0 + r)*PD + c*4);
            *reinterpret_cast<float4*>(&prs[(q*32 + r)*132 + c*4]) = v;
        }
        __syncthreads();
        // ---- K loads early: latency hides under bias ----
        const int j = j0 + lane;
        const float4* krp = reinterpret_cast<const float4*>(g_ks  + ((size_t)h*NT + j)*16);
        const float4* kpp = reinterpret_cast<const float4*>(g_kpg + ((size_t)h*NT + j)*12);
        float4 k0 = krp[0], k1 = krp[1], k2 = krp[2], k3 = krp[3];
        float4 p0 = kpp[0], p1 = kpp[1], p2 = kpp[2];
        // ---- fused pair-bias: 96 threads x (4 strided rows x 3 heads) ----
        if (t < 96) {
            const int rg = t >> 2, bg = t & 3;
            const float* w0 = wTs + (3*bg+0)*132;
            const float* w1 = wTs + (3*bg+1)*132;
            const float* w2 = wTs + (3*bg+2)*132;
            float b[4][3];
#pragma unroll
            for (int r = 0; r < 4; r++)
#pragma unroll
                for (int k = 0; k < 3; k++) b[r][k] = 0.f;
#pragma unroll 4
            for (int k4 = 0; k4 < 32; k4++) {
                float4 wa = *reinterpret_cast<const float4*>(w0 + k4*4);
                float4 wb = *reinterpret_cast<const float4*>(w1 + k4*4);
                float4 wc = *reinterpret_cast<const float4*>(w2 + k4*4);
#pragma unroll
                for (int r = 0; r < 4; r++) {
                    float4 v = *reinterpret_cast<const float4*>(
                        &prs[(rg + 24*r)*132 + k4*4]);
                    b[r][0] += v.x*wa.x + v.y*wa.y + v.z*wa.z + v.w*wa.w;
                    b[r][1] += v.x*wb.x + v.y*wb.y + v.z*wb.z + v.w*wb.w;
                    b[r][2] += v.x*wc.x + v.y*wc.y + v.z*wc.z + v.w*wc.w;
                }
            }
#pragma unroll
            for (int r = 0; r < 4; r++) {
                int row = rg + 24*r;
                int bq = row >> 5, br = row & 31;
#pragma unroll
                for (int k = 0; k < 3; k++)
                    bts[(bq*NH + 3*bg+k)*33 + br] =
                        (b[r][k] + bbs[3*bg+k]) * PAIR_SCALE;
            }
        }
        __syncthreads();
        // ---- logits + interleaved 3-q online softmax (warp h) ----
        {
            float s[TI];
#pragma unroll
            for (int q = 0; q < TI; q++) {
                const float4* qsv = reinterpret_cast<const float4*>(qss + (q*NH + h)*16);
                const float4* qpv = reinterpret_cast<const float4*>(qps + (q*NH + h)*12);
                float4 a0 = qsv[0], a1 = qsv[1], a2 = qsv[2], a3 = qsv[3];
                float sv = a0.x*k0.x + a0.y*k0.y + a0.z*k0.z + a0.w*k0.w
                         + a1.x*k1.x + a1.y*k1.y + a1.z*k1.z + a1.w*k1.w
                         + a2.x*k2.x + a2.y*k2.y + a2.z*k2.z + a2.w*k2.w
                         + a3.x*k3.x + a3.y*k3.y + a3.z*k3.z + a3.w*k3.w;
                sv *= SCALAR_SCALE;
                float4 b0 = qpv[0], b1 = qpv[1], b2 = qpv[2];
                float dx, dist = 0.f;
                dx = b0.x-p0.x; dist += dx*dx; dx = b0.y-p0.y; dist += dx*dx;
                dx = b0.z-p0.z; dist += dx*dx; dx = b0.w-p0.w; dist += dx*dx;
                dx = b1.x-p1.x; dist += dx*dx; dx = b1.y-p1.y; dist += dx*dx;
                dx = b1.z-p1.z; dist += dx*dx; dx = b1.w-p1.w; dist += dx*dx;
                dx = b2.x-p2.x; dist += dx*dx; dx = b2.y-p2.y; dist += dx*dx;
                dx = b2.z-p2.z; dist += dx*dx; dx = b2.w-p2.w; dist += dx*dx;
                sv += pscale * dist;
                sv += bts[(q*NH + h)*33 + lane];
                s[q] = sv;
            }
            float mx[TI];
#pragma unroll
            for (int q = 0; q < TI; q++) mx[q] = s[q];
#pragma unroll
            for (int o = 16; o; o >>= 1) {
#pragma unroll
                for (int q = 0; q < TI; q++)
                    mx[q] = fmaxf(mx[q], __shfl_xor_sync(~0u, mx[q], o));
            }
            float mold[TI], mnew[TI], ps[TI];
#pragma unroll
            for (int q = 0; q < TI; q++) {
                mold[q] = mst[q*NH + h];
                mnew[q] = fmaxf(mold[q], mx[q]);
                float p = __expf(s[q] - mnew[q]);
                pps[(q*16 + h)*33 + lane] = p;
                ps[q] = p;
            }
#pragma unroll
            for (int o = 16; o; o >>= 1) {
#pragma unroll
                for (int q = 0; q < TI; q++)
                    ps[q] += __shfl_xor_sync(~0u, ps[q], o);
            }
            if (lane == 0) {
#pragma unroll
                for (int q = 0; q < TI; q++) {
                    float f = __expf(mold[q] - mnew[q]);
                    facs[q*16 + h] = f;
                    lst[q*NH + h] = lst[q*NH + h]*f + ps[q];
                    mst[q*NH + h] = mnew[q];
                }
            }
        }
        __syncthreads();
        // ---- pair accumulate via tf32 mma (2-term compensated) ----
        {
            // rescale persistent fragments
            float flo = facs[qm*16 + mr];
            float fhi = facs[qm*16 + mr + 8];
#pragma unroll
            for (int nt = 0; nt < 4; nt++) {
                cfr[nt][0] *= flo; cfr[nt][1] *= flo;
                cfr[nt][2] *= fhi; cfr[nt][3] *= fhi;
            }
#pragma unroll
            for (int ks = 0; ks < 4; ks++) {
                const int kk = ks*8;
                // A fragment: P[16 x 8] from pps (rows 12..15 zero)
                float fa0 = pps[(qm*16 + mr     )*33 + kk + mc];
                float fa1 = pps[(qm*16 + mr + 8 )*33 + kk + mc];
                float fa2 = pps[(qm*16 + mr     )*33 + kk + mc + 4];
                float fa3 = pps[(qm*16 + mr + 8 )*33 + kk + mc + 4];
                uint32_t a0h = cvt_tf32(fa0), a1h = cvt_tf32(fa1);
                uint32_t a2h = cvt_tf32(fa2), a3h = cvt_tf32(fa3);
                uint32_t a0l = cvt_tf32(fa0 - __uint_as_float(a0h));
                uint32_t a1l = cvt_tf32(fa1 - __uint_as_float(a1h));
                uint32_t a2l = cvt_tf32(fa2 - __uint_as_float(a2h));
                uint32_t a3l = cvt_tf32(fa3 - __uint_as_float(a3h));
                const float* bbase = prs + (qm*32 + kk)*132;
#pragma unroll
                for (int nt = 0; nt < 4; nt++) {
                    const int n0 = wn*32 + nt*8;
                    float fb0 = bbase[ mc     *132 + n0 + mr];
                    float fb1 = bbase[(mc + 4)*132 + n0 + mr];
                    uint32_t b0h = cvt_tf32(fb0);
                    uint32_t b1h = cvt_tf32(fb1);
                    uint32_t b0l = cvt_tf32(fb0 - __uint_as_float(b0h));
                    uint32_t b1l = cvt_tf32(fb1 - __uint_as_float(b1h));
                    mma_tf32(cfr[nt][0], cfr[nt][1], cfr[nt][2], cfr[nt][3],
                             a0h, a1h, a2h, a3h, b0h, b1h);
                    mma_tf32(cfr[nt][0], cfr[nt][1], cfr[nt][2], cfr[nt][3],
                             a0h, a1h, a2h, a3h, b0l, b1l);
                    mma_tf32(cfr[nt][0], cfr[nt][1], cfr[nt][2], cfr[nt][3],
                             a0l, a1l, a2l, a3l, b0h, b1h);
                }
            }
        }
        // ---- scalar/point accumulate ----
        if (has_sp) {
            float f = facs[q2*16 + hh2];
            spacc.x *= f; spacc.y *= f; spacc.z *= f; spacc.w *= f;
            const float* pph = pps + (q2*16 + hh2)*33;
            const float* src = vbase + (size_t)j0*vstride;
#pragma unroll 8
            for (int jv = 0; jv < 32; jv++) {
                float p = pph[jv];
                float4 v = *reinterpret_cast<const float4*>(src + (size_t)jv*vstride);
                spacc.x += p*v.x; spacc.y += p*v.y; spacc.z += p*v.z; spacc.w += p*v.w;
            }
        }
        __syncthreads();
    }

    // ---- write accumulators to smem ----
    if (has_sp) {
        int off = (c2 < 4) ? c2*4 : 16 + (c2-4)*4;
        *reinterpret_cast<float4*>(accs + (q2*NH + hh2)*168 + off) = spacc;
    }
#pragma unroll
    for (int nt = 0; nt < 4; nt++) {
        const int n0 = wn*32 + nt*8;
        float* d0 = accs + (qm*NH + mr)*168 + 40 + n0 + 2*mc;
        d0[0] = cfr[nt][0];
        d0[1] = cfr[nt][1];
        if (mr + 8 < NH) {
            float* d1 = accs + (qm*NH + mr + 8)*168 + 40 + n0 + 2*mc;
            d1[0] = cfr[nt][2];
            d1[1] = cfr[nt][3];
        }
    }
    __syncthreads();

    // ---- finalize ----
    for (int e = t; e < TI*NH*16; e += 384) {
        int q = e / (NH*16), rem = e % (NH*16);
        int hh = rem/16, d = rem%16;
        g_feats[(size_t)(i0+q)*FEAT + hh*16 + d] =
            accs[(q*NH+hh)*168 + d] / lst[q*NH+hh];
    }
    for (int e = t; e < TI*NH*8; e += 384) {
        int q = e / (NH*8), rem = e % (NH*8);
        int hh = rem/8, p = rem%8;
        float inv = 1.f / lst[q*NH+hh];
        const float* R = Rs + q*9;
        const float* tv = tvs + q*3;
        const float* ac = accs + (q*NH+hh)*168 + 16 + p*3;
        float gx = ac[0]*inv - tv[0];
        float gy = ac[1]*inv - tv[1];
        float gz = ac[2]*inv - tv[2];
        float lx = R[0]*gx + R[3]*gy + R[6]*gz;
        float ly = R[1]*gx + R[4]*gy + R[7]*gz;
        float lz = R[2]*gx + R[5]*gy + R[8]*gz;
        float* fo = g_feats + (size_t)(i0+q)*FEAT;
        fo[192 + hh*24 + p*3 + 0] = lx;
        fo[192 + hh*24 + p*3 + 1] = ly;
        fo[192 + hh*24 + p*3 + 2] = lz;
        fo[480 + hh*8 + p] = sqrtf(lx*lx + ly*ly + lz*lz + 1e-8f);
    }
    for (int e = t; e < TI*NH*PD; e += 384) {
        int q = e / (NH*PD), rem = e % (NH*PD);
        int hh = rem/PD, d = rem%PD;
        g_feats[(size_t)(i0+q)*FEAT + 576 + hh*PD + d] =
            accs[(q*NH+hh)*168 + 40 + d] / lst[q*NH+hh];
    }
}

// ------------- launch -------------
extern "C" void kernel_launch(void* const* d_in, const int* in_sizes, int n_in,
                              void* d_out, int out_size)
{
    (void)in_sizes; (void)n_in; (void)out_size;
    const float* x     = (const float*)d_in[0];
    const float* pair  = (const float*)d_in[1];
    const float* rot   = (const float*)d_in[2];
    const float* trans = (const float*)d_in[3];
    const float* Wq    = (const float*)d_in[4];
    const float* Wk    = (const float*)d_in[5];
    const float* Wv    = (const float*)d_in[6];
    const float* Wpq   = (const float*)d_in[7];
    const float* Wpk   = (const float*)d_in[8];
    const float* Wpv   = (const float*)d_in[9];
    const float* Wpb   = (const float*)d_in[10];
    const float* bpb   = (const float*)d_in[11];
    const float* pwts  = (const float*)d_in[12];
    const float* Wout  = (const float*)d_in[13];
    const float* bout  = (const float*)d_in[14];
    float* out = (float*)d_out;

    cudaFuncSetAttribute(attn_k, cudaFuncAttributeMaxDynamicSharedMemorySize,
                         SMEM_FLOATS * 4);

    void *p_wall, *p_proj, *p_feats, *p_part;
    cudaGetSymbolAddress(&p_wall,  g_wall);
    cudaGetSymbolAddress(&p_proj,  g_proj);
    cudaGetSymbolAddress(&p_feats, g_feats);
    cudaGetSymbolAddress(&p_part,  g_part);

    pack_w<<<(DIM*NPROJ + 255)/256, 256>>>(Wq, Wk, Wv, Wpq, Wpk, Wpv);
    {
        dim3 g(NPROJ/64, NT/64, 1);
        sgemm_sk<<<g, 128>>>(x, (const float*)p_wall, (float*)p_proj,
                             NT, NPROJ, DIM);
    }
    relayout<<<NT, 128>>>(rot, trans);
    attn_k<<<NT/TI, 384, SMEM_FLOATS*4>>>(pair, rot, trans, pwts, Wpb, bpb);
    {
        dim3 g(DIM/64, NT/64, SPLITK);
        sgemm_sk<<<g, 128>>>((const float*)p_feats, Wout, (float*)p_part,
                             NT, DIM, FEAT);
    }
    reduce_k<<<(NT*DIM + 255)/256, 256>>>(out, bout);
}